// round 10
// baseline (speedup 1.0000x reference)
#include <cuda_runtime.h>
#include <cuda_fp16.h>
#include <math_constants.h>
#include <cstdint>

typedef unsigned char u8;

#define E_FIXED 32
#define B_FIXED 256
#define MAX_ELS_FIXED 65536
#define NODES_PER_BLK 8
#define META_BLOCKS 512
#define ROW_BLOCKS (MAX_ELS_FIXED / 8)     // 8192 (8 rows per block, 1 warp/row)
#define N_EDGES_FIXED (32768 * E_FIXED)    // 1048576

// Quantized exp table: q12 = round(exp(x) / rowmax * 4095)
__device__ u8      g_hi[(size_t)MAX_ELS_FIXED * 256];   // q >> 4            (16 MB)
__device__ u8      g_lo[(size_t)MAX_ELS_FIXED * 128];   // packed lo-nibbles  (8 MB)
__device__ float   g_scale[MAX_ELS_FIXED];              // rowmax / 4095
__device__ __half  g_w16[N_EDGES_FIXED];                // params[pids] as fp16 (2 MB)

// ---------------------------------------------------------------------------
// Kernel 1: builds the 12-bit table (row blocks) AND the edge-weight table
// (meta blocks, which run during k1's DRAM-bound window using idle LTS).
// ---------------------------------------------------------------------------
__global__ __launch_bounds__(256) void build_tables_kernel(
    const float* __restrict__ em,
    const float* __restrict__ params,
    const int*   __restrict__ pids)
{
    const int t = threadIdx.x;

    if (blockIdx.x < META_BLOCKS) {
        // w16[i] = (half) params[pids[i]] — 8 edges per thread, coalesced.
        const int base = blockIdx.x * (256 * 8);
#pragma unroll
        for (int i = 0; i < 8; ++i) {
            const int idx = base + i * 256 + t;
            g_w16[idx] = __float2half(params[__ldcs(&pids[idx])]);
        }
    } else {
        const int b    = blockIdx.x - META_BLOCKS;
        const int row  = b * 8 + (t >> 5);
        const int lane = t & 31;

        const size_t src = (size_t)row * B_FIXED + (lane << 3);
        const float4 a = __ldcs(reinterpret_cast<const float4*>(em + src));
        const float4 c = __ldcs(reinterpret_cast<const float4*>(em + src + 4));

        float e[8];
        e[0] = __expf(a.x); e[1] = __expf(a.y);
        e[2] = __expf(a.z); e[3] = __expf(a.w);
        e[4] = __expf(c.x); e[5] = __expf(c.y);
        e[6] = __expf(c.z); e[7] = __expf(c.w);

        float m = e[0];
#pragma unroll
        for (int i = 1; i < 8; ++i) m = fmaxf(m, e[i]);
#pragma unroll
        for (int s = 16; s > 0; s >>= 1)
            m = fmaxf(m, __shfl_xor_sync(0xffffffffu, m, s));

        const float rq = __fdividef(4095.0f, m);
        unsigned q[8];
#pragma unroll
        for (int i = 0; i < 8; ++i) q[i] = __float2uint_rn(e[i] * rq);

        uint2 hi;
        hi.x = (q[0] >> 4) | ((q[1] >> 4) << 8) | ((q[2] >> 4) << 16) | ((q[3] >> 4) << 24);
        hi.y = (q[4] >> 4) | ((q[5] >> 4) << 8) | ((q[6] >> 4) << 16) | ((q[7] >> 4) << 24);
        unsigned lo = (q[0] & 15u)        | ((q[1] & 15u) << 4)
                    | ((q[2] & 15u) << 8) | ((q[3] & 15u) << 12)
                    | ((q[4] & 15u) << 16)| ((q[5] & 15u) << 20)
                    | ((q[6] & 15u) << 24)| ((q[7] & 15u) << 28);

        *reinterpret_cast<uint2*>(g_hi + (size_t)row * 256 + (lane << 3)) = hi;
        *reinterpret_cast<unsigned*>(g_lo + (size_t)row * 128 + (lane << 2)) = lo;
        if (lane == 0) g_scale[row] = m * (1.0f / 4095.0f);
    }

    cudaTriggerProgrammaticLaunchCompletion();
}

// ---------------------------------------------------------------------------
// Kernel 2: out[nids[n], :] = log( sum_e w_e * dequant(q12[cids[n,e], :]) )
// One warp per node; lane owns 8 batch cols. Decode via PRMT fp16 magic
// constants (no cvt pipe); HFMA2 accumulate in groups of 8 edges, fp32 flush.
// ---------------------------------------------------------------------------
__global__ __launch_bounds__(256) void sum_layer_e32_q12_kernel(
    const int*   __restrict__ nids,
    const int*   __restrict__ cids,
    float*       __restrict__ out)
{
    const int t    = threadIdx.x;
    const int wn   = t >> 5;
    const int lane = t & 31;
    const int boff = lane << 3;

    __shared__ int2 meta[NODES_PER_BLK][E_FIXED];   // (cid, half2(m,m))

    // Pre-sync: stage cid (pure input) while kernel 1 drains.
    const int gi  = blockIdx.x * 256 + t;           // node-major edge index
    const int cid = __ldcs(&cids[gi]);

    cudaGridDependencySynchronize();                // k1 tables now complete

    {
        const float w  = __half2float(g_w16[gi]);
        const float sp = g_scale[cid];              // 256KB, L1-resident
        const unsigned short mu =
            __half_as_ushort(__float2half(w * sp)); // m = w * rowmax/4095
        meta[wn][lane] = make_int2(cid, (int)mu | ((int)mu << 16));
    }
    __syncwarp();

    const u8* base_hi = g_hi + boff;                // lane offsets folded in
    const u8* base_lo = g_lo + (lane << 2);

    const __half2 C_HI = __halves2half2(__ushort_as_half(0x7400),
                                        __ushort_as_half(0x7400)); // 16384
    const __half2 C_LO = __halves2half2(__ushort_as_half(0x6400),
                                        __ushort_as_half(0x6400)); // 1024

    float acc0 = 0.f, acc1 = 0.f, acc2 = 0.f, acc3 = 0.f;
    float acc4 = 0.f, acc5 = 0.f, acc6 = 0.f, acc7 = 0.f;

#pragma unroll
    for (int g = 0; g < E_FIXED / 8; ++g) {
        __half2 h0 = __halves2half2(__ushort_as_half(0), __ushort_as_half(0));
        __half2 h1 = h0, h2 = h0, h3 = h0;

#pragma unroll
        for (int e = 0; e < 8; ++e) {
            const int2 mv = meta[wn][g * 8 + e];
            __half2 m2;
            *reinterpret_cast<unsigned*>(&m2) = (unsigned)mv.y;

            const uint2    hv = *reinterpret_cast<const uint2*>(
                base_hi + (size_t)mv.x * 256);
            const unsigned nv = *reinterpret_cast<const unsigned*>(
                base_lo + (size_t)mv.x * 128);
            const unsigned s1 = nv >> 4;

            // q = hi*16 + nib, reconstructed as fp16:
            //   hp = 0x74:hi pairs -> fp16 16384 + 16*hi  (sub C_HI)
            //   np = 0x64:(nib)    -> fp16 1024 + nib     (sub C_LO)
#define Q12_PAIR(HWORD, NSEL, HSEL, HACC)                                     \
            do {                                                              \
                unsigned hp = __byte_perm((HWORD), 0x74747474u, (HSEL));      \
                __half2 h16 = __hsub2(*reinterpret_cast<__half2*>(&hp), C_HI);\
                unsigned npr = __byte_perm(nv, s1, (NSEL));                   \
                unsigned np = (npr & 0x000F000Fu) | 0x64006400u;              \
                __half2 n16 = __hsub2(*reinterpret_cast<__half2*>(&np), C_LO);\
                __half2 q2  = __hadd2(h16, n16);                              \
                HACC = __hfma2(q2, m2, HACC);                                 \
            } while (0)

            Q12_PAIR(hv.x, 0x0400u, 0x4140u, h0);
            Q12_PAIR(hv.x, 0x1511u, 0x4342u, h1);
            Q12_PAIR(hv.y, 0x2622u, 0x4140u, h2);
            Q12_PAIR(hv.y, 0x3733u, 0x4342u, h3);
#undef Q12_PAIR
        }

        const float2 f0 = __half22float2(h0);
        const float2 f1 = __half22float2(h1);
        const float2 f2 = __half22float2(h2);
        const float2 f3 = __half22float2(h3);
        acc0 += f0.x; acc1 += f0.y;
        acc2 += f1.x; acc3 += f1.y;
        acc4 += f2.x; acc5 += f2.y;
        acc6 += f3.x; acc7 += f3.y;
    }

    float4 o0, o1;
    o0.x = __logf(fmaxf(acc0, 1e-30f));
    o0.y = __logf(fmaxf(acc1, 1e-30f));
    o0.z = __logf(fmaxf(acc2, 1e-30f));
    o0.w = __logf(fmaxf(acc3, 1e-30f));
    o1.x = __logf(fmaxf(acc4, 1e-30f));
    o1.y = __logf(fmaxf(acc5, 1e-30f));
    o1.z = __logf(fmaxf(acc6, 1e-30f));
    o1.w = __logf(fmaxf(acc7, 1e-30f));

    const int nid = __ldg(&nids[blockIdx.x * NODES_PER_BLK + wn]);
    float* op = out + (size_t)nid * B_FIXED + boff;
    __stcs(reinterpret_cast<float4*>(op),     o0);
    __stcs(reinterpret_cast<float4*>(op + 4), o1);
}

// ---------------------------------------------------------------------------
// Generic fallback (reference-faithful two-pass with max stabilization).
// ---------------------------------------------------------------------------
__global__ void sum_layer_generic_kernel(
    const float* __restrict__ element_mars,
    const float* __restrict__ params,
    const int*   __restrict__ nids,
    const int*   __restrict__ cids,
    const int*   __restrict__ pids,
    float*       __restrict__ out,
    int E, int B)
{
    const int n = blockIdx.x;
    for (int t = threadIdx.x; t < B; t += blockDim.x) {
        float m = -CUDART_INF_F;
        for (int e = 0; e < E; ++e) {
            float x = element_mars[(size_t)cids[(size_t)n * E + e] * B + t];
            m = fmaxf(m, x);
        }
        float s = 0.0f;
        for (int e = 0; e < E; ++e) {
            float x = element_mars[(size_t)cids[(size_t)n * E + e] * B + t];
            float w = params[pids[(size_t)n * E + e]];
            s = fmaf(__expf(x - m), w, s);
        }
        out[(size_t)nids[n] * B + t] = __logf(fmaxf(s, 1e-10f)) + m;
    }
}

extern "C" void kernel_launch(void* const* d_in, const int* in_sizes, int n_in,
                              void* d_out, int out_size)
{
    const float* node_mars    = (const float*)d_in[0];
    const float* element_mars = (const float*)d_in[1];
    const float* params       = (const float*)d_in[2];
    const int*   nids         = (const int*)d_in[3];
    const int*   cids         = (const int*)d_in[4];
    const int*   pids         = (const int*)d_in[5];

    const int N = in_sizes[3];
    const int B = in_sizes[0] / N;
    const int E = in_sizes[4] / N;
    const long long els_total = in_sizes[1];

    float* out = (float*)d_out;

    if (E == E_FIXED && B == B_FIXED &&
        els_total == (long long)MAX_ELS_FIXED * B_FIXED &&
        N * E_FIXED == N_EDGES_FIXED &&
        (N % NODES_PER_BLK) == 0 &&
        (size_t)N * B == (size_t)out_size) {
        build_tables_kernel<<<META_BLOCKS + ROW_BLOCKS, 256>>>(
            element_mars, params, pids);

        cudaLaunchConfig_t cfg = {};
        cfg.gridDim  = dim3(N / NODES_PER_BLK);
        cfg.blockDim = dim3(256);
        cfg.dynamicSmemBytes = 0;
        cfg.stream = 0;
        cudaLaunchAttribute attrs[1];
        attrs[0].id = cudaLaunchAttributeProgrammaticStreamSerialization;
        attrs[0].val.programmaticStreamSerializationAllowed = 1;
        cfg.attrs = attrs;
        cfg.numAttrs = 1;
        cudaLaunchKernelEx(&cfg, sum_layer_e32_q12_kernel, nids, cids, out);
    } else {
        cudaMemcpyAsync(out, node_mars, sizeof(float) * (size_t)out_size,
                        cudaMemcpyDeviceToDevice);
        int threads = (B < 256) ? B : 256;
        sum_layer_generic_kernel<<<N, threads>>>(element_mars, params, nids, cids,
                                                 pids, out, E, B);
    }
}

// round 11
// speedup vs baseline: 1.4752x; 1.4752x over previous
#include <cuda_runtime.h>
#include <cuda_fp16.h>
#include <math_constants.h>
#include <cstdint>

#define E_FIXED 32
#define B_FIXED 256
#define MAX_ELS_FIXED 65536
#define NODES_PER_BLK 8        // kernel2: one warp per node
#define META_BLOCKS 512
#define EXP_BLOCKS 8192        // 16.78M elements / (256 thr * 8 el)
#define N_EDGES_FIXED (32768 * E_FIXED)   // 1048576

// 32 MB scratch: exp(element_mars) in fp16. Static __device__ array (no alloc).
__device__ __half g_expm[(size_t)MAX_ELS_FIXED * B_FIXED];
// Edge weights prefetched in kernel 1 (params[pids], fp32, 4 MB).
__device__ float  g_w32[N_EDGES_FIXED];

// ---------------------------------------------------------------------------
// Kernel 1: (a) meta blocks (first 512): g_w32 = params[pids] — the scattered
// params gather runs here, inside the DRAM-bound window where LTS has
// headroom, instead of inside kernel 2's LTS-capped window.
// (b) exp blocks: g_expm = (half) exp(element_mars), 8 elements/thread.
// ---------------------------------------------------------------------------
__global__ __launch_bounds__(256) void build_tables_kernel(
    const float* __restrict__ em,
    const float* __restrict__ params,
    const int*   __restrict__ pids)
{
    const int t = threadIdx.x;

    if (blockIdx.x < META_BLOCKS) {
        const int base = blockIdx.x * (256 * 8);
#pragma unroll
        for (int i = 0; i < 8; ++i) {
            const int idx = base + i * 256 + t;
            g_w32[idx] = params[__ldcs(&pids[idx])];
        }
    } else {
        const size_t i =
            ((size_t)(blockIdx.x - META_BLOCKS) * 256 + t) * 8;
        const float4 a = __ldcs(reinterpret_cast<const float4*>(em + i));
        const float4 b = __ldcs(reinterpret_cast<const float4*>(em + i + 4));

        __half2 h[4];
        h[0] = __floats2half2_rn(__expf(a.x), __expf(a.y));
        h[1] = __floats2half2_rn(__expf(a.z), __expf(a.w));
        h[2] = __floats2half2_rn(__expf(b.x), __expf(b.y));
        h[3] = __floats2half2_rn(__expf(b.z), __expf(b.w));

        *reinterpret_cast<uint4*>(g_expm + i) =
            *reinterpret_cast<const uint4*>(h);
    }

    cudaTriggerProgrammaticLaunchCompletion();
}

// ---------------------------------------------------------------------------
// Kernel 2: out[nids[n], :] = log( sum_e w[n,e] * g_expm[cids[n,e], :] )
// Round-5 core (proven 39.8us): one warp per node; lane owns 8 batch columns
// (one LDG.128 of 8 halves); fp32 accumulate; fully static unroll-8 loop.
// Only change: w comes from the coalesced g_w32 prefetch (post-sync) instead
// of a scattered params gather (-32MB of k2 LTS sector traffic).
// ---------------------------------------------------------------------------
__global__ __launch_bounds__(256) void sum_layer_e32_h_kernel(
    const float* __restrict__ nids_dummy_params,   // unused (kept slot)
    const int*   __restrict__ nids,
    const int*   __restrict__ cids,
    float*       __restrict__ out)
{
    const int t    = threadIdx.x;
    const int wn   = t >> 5;          // warp index = local node 0..7
    const int lane = t & 31;
    const int boff = lane << 3;       // 8 halves per lane

    // meta.x = cid, meta.y = float bits of w.
    __shared__ int2 meta[NODES_PER_BLK][E_FIXED];

    // Pre-sync: stage cid (pure input) while kernel 1 drains (PDL window).
    const int gi  = blockIdx.x * 256 + t;    // node-major edge index
    const int cid = __ldcs(&cids[gi]);
    meta[wn][lane].x = cid;

    // Wait for kernel 1's tables (g_expm, g_w32) to be complete & visible.
    cudaGridDependencySynchronize();

    meta[wn][lane].y = __float_as_int(g_w32[gi]);   // coalesced, 4 MB total
    __syncwarp();

    const __half* row_base = g_expm + boff;

    float acc0 = 0.f, acc1 = 0.f, acc2 = 0.f, acc3 = 0.f;
    float acc4 = 0.f, acc5 = 0.f, acc6 = 0.f, acc7 = 0.f;

#pragma unroll 8
    for (int e = 0; e < E_FIXED; ++e) {
        const int2  m = meta[wn][e];
        const float w = __int_as_float(m.y);
        const uint4 u = *reinterpret_cast<const uint4*>(
            row_base + (size_t)m.x * B_FIXED);
        const __half2* hp = reinterpret_cast<const __half2*>(&u);
        const float2 f0 = __half22float2(hp[0]);
        const float2 f1 = __half22float2(hp[1]);
        const float2 f2 = __half22float2(hp[2]);
        const float2 f3 = __half22float2(hp[3]);
        acc0 = fmaf(f0.x, w, acc0);
        acc1 = fmaf(f0.y, w, acc1);
        acc2 = fmaf(f1.x, w, acc2);
        acc3 = fmaf(f1.y, w, acc3);
        acc4 = fmaf(f2.x, w, acc4);
        acc5 = fmaf(f2.y, w, acc5);
        acc6 = fmaf(f3.x, w, acc6);
        acc7 = fmaf(f3.y, w, acc7);
    }

    float4 o0, o1;
    o0.x = __logf(fmaxf(acc0, 1e-30f));
    o0.y = __logf(fmaxf(acc1, 1e-30f));
    o0.z = __logf(fmaxf(acc2, 1e-30f));
    o0.w = __logf(fmaxf(acc3, 1e-30f));
    o1.x = __logf(fmaxf(acc4, 1e-30f));
    o1.y = __logf(fmaxf(acc5, 1e-30f));
    o1.z = __logf(fmaxf(acc6, 1e-30f));
    o1.w = __logf(fmaxf(acc7, 1e-30f));

    const int nid = __ldg(&nids[blockIdx.x * NODES_PER_BLK + wn]);
    float* op = out + (size_t)nid * B_FIXED + boff;
    // Streaming stores: don't let the 32MB output evict the table from L2.
    __stcs(reinterpret_cast<float4*>(op),     o0);
    __stcs(reinterpret_cast<float4*>(op + 4), o1);
}

// ---------------------------------------------------------------------------
// Generic fallback (reference-faithful two-pass with max stabilization).
// ---------------------------------------------------------------------------
__global__ void sum_layer_generic_kernel(
    const float* __restrict__ element_mars,
    const float* __restrict__ params,
    const int*   __restrict__ nids,
    const int*   __restrict__ cids,
    const int*   __restrict__ pids,
    float*       __restrict__ out,
    int E, int B)
{
    const int n = blockIdx.x;
    for (int t = threadIdx.x; t < B; t += blockDim.x) {
        float m = -CUDART_INF_F;
        for (int e = 0; e < E; ++e) {
            float x = element_mars[(size_t)cids[(size_t)n * E + e] * B + t];
            m = fmaxf(m, x);
        }
        float s = 0.0f;
        for (int e = 0; e < E; ++e) {
            float x = element_mars[(size_t)cids[(size_t)n * E + e] * B + t];
            float w = params[pids[(size_t)n * E + e]];
            s = fmaf(__expf(x - m), w, s);
        }
        out[(size_t)nids[n] * B + t] = __logf(fmaxf(s, 1e-10f)) + m;
    }
}

extern "C" void kernel_launch(void* const* d_in, const int* in_sizes, int n_in,
                              void* d_out, int out_size)
{
    const float* node_mars    = (const float*)d_in[0];
    const float* element_mars = (const float*)d_in[1];
    const float* params       = (const float*)d_in[2];
    const int*   nids         = (const int*)d_in[3];
    const int*   cids         = (const int*)d_in[4];
    const int*   pids         = (const int*)d_in[5];

    const int N = in_sizes[3];
    const int B = in_sizes[0] / N;
    const int E = in_sizes[4] / N;
    const long long els_total = in_sizes[1];

    float* out = (float*)d_out;

    if (E == E_FIXED && B == B_FIXED &&
        els_total == (long long)MAX_ELS_FIXED * B_FIXED &&
        N * E_FIXED == N_EDGES_FIXED &&
        (N % NODES_PER_BLK) == 0 &&
        (size_t)N * B == (size_t)out_size) {
        build_tables_kernel<<<META_BLOCKS + EXP_BLOCKS, 256>>>(
            element_mars, params, pids);

        // PDL: kernel 2 starts (cid staging) while kernel 1 drains;
        // gridDependencySynchronize gates the table + w32 reads.
        cudaLaunchConfig_t cfg = {};
        cfg.gridDim  = dim3(N / NODES_PER_BLK);
        cfg.blockDim = dim3(256);
        cfg.dynamicSmemBytes = 0;
        cfg.stream = 0;
        cudaLaunchAttribute attrs[1];
        attrs[0].id = cudaLaunchAttributeProgrammaticStreamSerialization;
        attrs[0].val.programmaticStreamSerializationAllowed = 1;
        cfg.attrs = attrs;
        cfg.numAttrs = 1;
        cudaLaunchKernelEx(&cfg, sum_layer_e32_h_kernel,
                           (const float*)nullptr, nids, cids, out);
    } else {
        cudaMemcpyAsync(out, node_mars, sizeof(float) * (size_t)out_size,
                        cudaMemcpyDeviceToDevice);
        int threads = (B < 256) ? B : 256;
        sum_layer_generic_kernel<<<N, threads>>>(element_mars, params, nids, cids,
                                                 pids, out, E, B);
    }
}